// round 17
// baseline (speedup 1.0000x reference)
#include <cuda_runtime.h>

// ParallelBellowsLayers: per-channel 1->16->1 MLP with ReLU, C=40000, B=128, E=16.
// out[b,c] = relu( sum_e relu(x[b,c]*w1[c,e]+b1[c,e]) * w2[c,e] + b2[c] )
// Output (B,2,20000) == (B,C) row-major -> elementwise in x's layout.
// b1[c,:]==0 (this dataset) => sum_e relu(x*w1e)*w2e == x * (x>0 ? s_pos : s_neg).
//
// Final form (R17). 16 rounds established: total == mandatory traffic
// (~49.7MB: x 20.5 + weights 7.7 + params 1.0 + out 20.5) / ~4.6 TB/s achieved
// aggregate, invariant to occupancy, MLP depth, vector width, cp.async, TMA,
// wave shape, and L2 residency policy (each < +-0.3us). This version keeps the
// proven winners (collapsed per-channel form, PDL overlap of precompute under
// apply's x-loads, RROWS=8 depth-3 pipelined streaming, one-wave grid) and
// strips the dead policy machinery. NaN-flag in s_pos routes nonzero-b1 /
// non-finite channels to an exact per-element fallback (never taken here).

#define NGENES 20000
#define NTECH  2
#define CC     (NGENES * NTECH)   // 40000
#define BB     128
#define EE     16
#define NG     (CC / 4)           // 10000 float4 channel-groups
#define RROWS  8                  // batch rows per thread in apply

// SoA per-channel params (NaN in g_sp[c] => exact-fallback channel)
__device__ float g_sp[CC];
__device__ float g_sn[CC];
__device__ float g_bf[CC];

// ---- memory ops (no cache-policy operands: proven worthless R14-R16) -------
__device__ __forceinline__ float4 ldg4(const float* p)
{
    float4 v;
    asm volatile("ld.global.nc.v4.f32 {%0,%1,%2,%3}, [%4];"
                 : "=f"(v.x), "=f"(v.y), "=f"(v.z), "=f"(v.w) : "l"(p));
    return v;
}
__device__ __forceinline__ void stg4(float* p, float4 v)
{
    asm volatile("st.global.v4.f32 [%0], {%1,%2,%3,%4};"
                 :: "l"(p), "f"(v.x), "f"(v.y), "f"(v.z), "f"(v.w) : "memory");
}
// -----------------------------------------------------------------------------

// Precompute: 4 threads per channel, shfl-reduced; signals dependents early.
__global__ void __launch_bounds__(256)
precompute_kernel(const float* __restrict__ w1,
                  const float* __restrict__ b1,
                  const float* __restrict__ w2,
                  const float* __restrict__ b2)
{
    int t = blockIdx.x * 256 + threadIdx.x;
    int c = t >> 2;
    int part = t & 3;
    if (c >= CC) return;   // exited threads satisfy launch_dependents

    size_t vi = (size_t)c * 4 + part;
    float4 a = __ldg(reinterpret_cast<const float4*>(w1) + vi);
    float4 z = __ldg(reinterpret_cast<const float4*>(b1) + vi);
    float4 w = __ldg(reinterpret_cast<const float4*>(w2) + vi);

    bool ok = (z.x == 0.f) && (z.y == 0.f) && (z.z == 0.f) && (z.w == 0.f);

    float sp = 0.f, sn = 0.f, p;
    p = a.x * w.x; sp += (a.x > 0.f) ? p : 0.f; sn += (a.x < 0.f) ? p : 0.f;
    p = a.y * w.y; sp += (a.y > 0.f) ? p : 0.f; sn += (a.y < 0.f) ? p : 0.f;
    p = a.z * w.z; sp += (a.z > 0.f) ? p : 0.f; sn += (a.z < 0.f) ? p : 0.f;
    p = a.w * w.w; sp += (a.w > 0.f) ? p : 0.f; sn += (a.w < 0.f) ? p : 0.f;

    if (!ok) sp = __int_as_float(0x7fc00000);   // NaN survives the reduction

    sp += __shfl_xor_sync(0xffffffffu, sp, 1);
    sp += __shfl_xor_sync(0xffffffffu, sp, 2);
    sn += __shfl_xor_sync(0xffffffffu, sn, 1);
    sn += __shfl_xor_sync(0xffffffffu, sn, 2);

    if (part == 0) {
        if (!isfinite(sp) || !isfinite(sn)) sp = __int_as_float(0x7fc00000);
        g_sp[c] = sp;
        g_sn[c] = sn;
        g_bf[c] = __ldg(b2 + c);
    }

    asm volatile("griddepcontrol.launch_dependents;");
}

// Exact per-element path for flagged channels (never taken on this dataset).
__device__ __noinline__ float bellows_exact(float xv, int c,
                                            const float* __restrict__ w1,
                                            const float* __restrict__ b1,
                                            const float* __restrict__ w2,
                                            float bias)
{
    float acc = 0.f;
    const float* w1r = w1 + (size_t)c * EE;
    const float* b1r = b1 + (size_t)c * EE;
    const float* w2r = w2 + (size_t)c * EE;
#pragma unroll 4
    for (int e = 0; e < EE; ++e) {
        float h = fmaxf(fmaf(xv, w1r[e], b1r[e]), 0.f);
        acc = fmaf(h, w2r[e], acc);
    }
    return fmaxf(acc + bias, 0.f);
}

__device__ __forceinline__ float bellows_fast(float xv, float sp, float sn, float bias)
{
    float s = (xv > 0.f) ? sp : sn;
    return fmaxf(fmaf(xv, s, bias), 0.f);
}

__global__ void __launch_bounds__(256, 5)   // <=51 regs: 5 blocks/SM -> 740
apply_kernel(const float* __restrict__ x,   // resident >= 640 grid = one wave
             const float* __restrict__ w1,
             const float* __restrict__ b1,
             const float* __restrict__ w2,
             float* __restrict__ out)
{
    int g = blockIdx.x * 256 + threadIdx.x;   // group of 4 channels
    if (g >= NG) return;
    int c  = g * 4;
    int b0 = blockIdx.y * RROWS;

    const float* xp = x + (size_t)b0 * CC + c;
    float*       op = out + (size_t)b0 * CC + c;

    // First x loads are independent of precompute: issue before the PDL wait
    // so the predecessor's tail hides under them. Depth-3 pipeline.
    float4 xa = ldg4(xp);
    float4 xb = ldg4(xp + (size_t)CC);
    float4 xc = ldg4(xp + (size_t)2 * CC);

    asm volatile("griddepcontrol.wait;" ::: "memory");

    float4 sp = ldg4(g_sp + c);
    float4 sn = ldg4(g_sn + c);
    float4 bf = ldg4(g_bf + c);

    bool any_fb = (sp.x != sp.x) || (sp.y != sp.y) || (sp.z != sp.z) || (sp.w != sp.w);

    if (!any_fb) {
        // depth-3 pipeline over 8 rows: load r+3 while computing/storing r.
#pragma unroll
        for (int r = 0; r < RROWS; ++r) {
            float4 xf;
            if (r + 3 < RROWS)
                xf = ldg4(xp + (size_t)(r + 3) * CC);
            float4 o;
            o.x = bellows_fast(xa.x, sp.x, sn.x, bf.x);
            o.y = bellows_fast(xa.y, sp.y, sn.y, bf.y);
            o.z = bellows_fast(xa.z, sp.z, sn.z, bf.z);
            o.w = bellows_fast(xa.w, sp.w, sn.w, bf.w);
            stg4(op + (size_t)r * CC, o);
            xa = xb;
            xb = xc;
            xc = xf;
        }
    } else {
#pragma unroll 2
        for (int r = 0; r < RROWS; ++r) {
            float4 xv = ldg4(xp + (size_t)r * CC);
            float4 o;
            o.x = (sp.x != sp.x) ? bellows_exact(xv.x, c + 0, w1, b1, w2, bf.x)
                                 : bellows_fast(xv.x, sp.x, sn.x, bf.x);
            o.y = (sp.y != sp.y) ? bellows_exact(xv.y, c + 1, w1, b1, w2, bf.y)
                                 : bellows_fast(xv.y, sp.y, sn.y, bf.y);
            o.z = (sp.z != sp.z) ? bellows_exact(xv.z, c + 2, w1, b1, w2, bf.z)
                                 : bellows_fast(xv.z, sp.z, sn.z, bf.z);
            o.w = (sp.w != sp.w) ? bellows_exact(xv.w, c + 3, w1, b1, w2, bf.w)
                                 : bellows_fast(xv.w, sp.w, sn.w, bf.w);
            stg4(op + (size_t)r * CC, o);
        }
    }
}

extern "C" void kernel_launch(void* const* d_in, const int* in_sizes, int n_in,
                              void* d_out, int out_size)
{
    const float* x  = (const float*)d_in[0];   // (128, 40000)
    const float* w1 = (const float*)d_in[1];   // (40000, 16)
    const float* b1 = (const float*)d_in[2];   // (40000, 16)
    const float* w2 = (const float*)d_in[3];   // (40000, 16)
    const float* b2 = (const float*)d_in[4];   // (40000,)
    float* out = (float*)d_out;                // (128, 2, 20000) == (128, 40000)

    precompute_kernel<<<(CC * 4 + 255) / 256, 256>>>(w1, b1, w2, b2);

    // apply: Programmatic Stream Serialization; begins while precompute
    // drains, griddepcontrol.wait provides the param-visibility ordering.
    cudaLaunchConfig_t cfg = {};
    cfg.gridDim  = dim3((NG + 255) / 256, BB / RROWS);   // (40, 16) = 640 blocks
    cfg.blockDim = dim3(256, 1, 1);
    cfg.dynamicSmemBytes = 0;
    cfg.stream = 0;

    cudaLaunchAttribute attrs[1];
    attrs[0].id = cudaLaunchAttributeProgrammaticStreamSerialization;
    attrs[0].val.programmaticStreamSerializationAllowed = 1;
    cfg.attrs = attrs;
    cfg.numAttrs = 1;

    cudaLaunchKernelEx(&cfg, apply_kernel, x, w1, b1, w2, out);
}